// round 4
// baseline (speedup 1.0000x reference)
#include <cuda_runtime.h>
#include <cstdint>
#include <cstddef>

#define DI __device__ __forceinline__

// ---------------------------------------------------------------------------
// Problem constants
// ---------------------------------------------------------------------------
namespace {
constexpr int B_   = 64;
constexpr int S_   = 2048;
constexpr int F_   = 40;
constexpr int EMB_ = 128;
constexpr int HID_ = 256;
constexpr int G_   = 4 * HID_;             // 1024 gate rows
constexpr long long MS = (long long)B_ * S_;   // 131072 flattened rows

// Recurrence kernel geometry
constexpr int CLU  = 8;                    // CTAs per cluster
constexpr int UPC  = HID_ / CLU;           // 32 hidden units per CTA
constexpr int ROWS = 4 * UPC;              // 128 gate rows per CTA
constexpr int BPC  = 4;                    // batch rows per cluster
constexpr int NTHR = ROWS * BPC;           // 512 threads

constexpr int WPAD = 260;                  // padded W row stride (floats): conflict-free LDS.128
constexpr int SM_W = ROWS * WPAD;          // 33280 floats
constexpr int SM_H = BPC * HID_;           // 1024 floats per h buffer
constexpr int SM_G = ROWS * BPC;           // 512 floats gate exchange
constexpr int SMEM_FLOATS = SM_W + 2 * SM_H + SM_G;     // 35840
constexpr size_t REC_SMEM = (size_t)SMEM_FLOATS * sizeof(float);  // 143360 B
}

// ---------------------------------------------------------------------------
// Scratch (device globals: no runtime allocation allowed)
// ---------------------------------------------------------------------------
__device__ float g_gx[(size_t)MS * G_];     // 536 MB: gate preactivations (reused L0/L1)
__device__ float g_hs[(size_t)MS * HID_];   // 134 MB: hidden states (reused L0/L1)
__device__ float g_Wc[G_ * F_];             // fused W_ih0 @ W_in
__device__ float g_b0[G_];                  // fused layer-0 bias
__device__ float g_b1[G_];                  // layer-1 bias

// ---------------------------------------------------------------------------
// f32x2 helpers (packed dual-FMA; ptxas won't emit from C++)
// ---------------------------------------------------------------------------
DI void ffma2(unsigned long long& acc, unsigned long long a, unsigned long long b) {
    asm("fma.rn.f32x2 %0, %1, %2, %0;" : "+l"(acc) : "l"(a), "l"(b));
}
DI unsigned long long dup2(float x) {
    unsigned long long d;
    unsigned u = __float_as_uint(x);
    asm("mov.b64 %0, {%1, %1};" : "=l"(d) : "r"(u));
    return d;
}
DI float lo2(unsigned long long v) { return __uint_as_float((unsigned)v); }
DI float hi2(unsigned long long v) { return __uint_as_float((unsigned)(v >> 32)); }

DI uint32_t s2u(const void* p) {
    uint32_t a;
    asm("{ .reg .u64 t; cvta.to.shared.u64 t, %1; cvt.u32.u64 %0, t; }"
        : "=r"(a) : "l"(p));
    return a;
}
DI void cluster_sync() {
    asm volatile("barrier.cluster.arrive.aligned;" ::: "memory");
    asm volatile("barrier.cluster.wait.aligned;" ::: "memory");
}
DI float sigf(float x) { return 1.f / (1.f + __expf(-x)); }

// ---------------------------------------------------------------------------
// Prep: Wc = W_ih0 @ W_in  (1024 x 40), fused biases
// ---------------------------------------------------------------------------
__global__ void prep_kernel(const float* __restrict__ Wih0, const float* __restrict__ Win,
                            const float* __restrict__ bin,
                            const float* __restrict__ bih0, const float* __restrict__ bhh0,
                            const float* __restrict__ bih1, const float* __restrict__ bhh1) {
    int idx = blockIdx.x * blockDim.x + threadIdx.x;
    if (idx < G_ * F_) {
        int g = idx / F_, f = idx % F_;
        float s = 0.f;
        #pragma unroll 8
        for (int e = 0; e < EMB_; e++) s += Wih0[g * EMB_ + e] * Win[e * F_ + f];
        g_Wc[idx] = s;
    }
    if (idx < G_) {
        float s = bih0[idx] + bhh0[idx];
        #pragma unroll 8
        for (int e = 0; e < EMB_; e++) s += Wih0[idx * EMB_ + e] * bin[e];
        g_b0[idx] = s;
        g_b1[idx] = bih1[idx] + bhh1[idx];
    }
}

// ---------------------------------------------------------------------------
// GEMM: C[M][N] = A[M][K] @ Bt[N][K] + bias[N]
// 128x128 tile, 256 threads, 8x8 per thread (f32x2 on M-pairs). K % 8 == 0.
// ---------------------------------------------------------------------------
__global__ __launch_bounds__(256) void gemm_bias_f32(
    const float* __restrict__ A, const float* __restrict__ Bt,
    const float* __restrict__ bias, float* __restrict__ C, int K, int N) {
    __shared__ float As[8][128];   // [k][m]
    __shared__ float Bs[8][128];   // [k][n]

    const int tid = threadIdx.x;
    const int m0 = blockIdx.y * 128, n0 = blockIdx.x * 128;
    const int lr = tid >> 1, lq = tid & 1;     // load: row, half (2 float4/row/chunk)
    const int ty = tid >> 4, tx = tid & 15;    // compute: 16x16

    unsigned long long acc[4][8];
    #pragma unroll
    for (int i = 0; i < 4; i++)
        #pragma unroll
        for (int j = 0; j < 8; j++) acc[i][j] = 0ull;

    for (int kc = 0; kc < K; kc += 8) {
        float4 av = *(const float4*)(A + (size_t)(m0 + lr) * K + kc + lq * 4);
        float4 bv = *(const float4*)(Bt + (size_t)(n0 + lr) * K + kc + lq * 4);
        __syncthreads();   // previous chunk's compute done before overwrite
        As[lq * 4 + 0][lr] = av.x; As[lq * 4 + 1][lr] = av.y;
        As[lq * 4 + 2][lr] = av.z; As[lq * 4 + 3][lr] = av.w;
        Bs[lq * 4 + 0][lr] = bv.x; Bs[lq * 4 + 1][lr] = bv.y;
        Bs[lq * 4 + 2][lr] = bv.z; Bs[lq * 4 + 3][lr] = bv.w;
        __syncthreads();
        #pragma unroll
        for (int k = 0; k < 8; k++) {
            ulonglong2 a01 = *(const ulonglong2*)&As[k][ty * 8];
            ulonglong2 a23 = *(const ulonglong2*)&As[k][ty * 8 + 4];
            float4 bl = *(const float4*)&Bs[k][tx * 8];
            float4 bh = *(const float4*)&Bs[k][tx * 8 + 4];
            unsigned long long ap[4] = { a01.x, a01.y, a23.x, a23.y };
            unsigned long long bd[8] = { dup2(bl.x), dup2(bl.y), dup2(bl.z), dup2(bl.w),
                                         dup2(bh.x), dup2(bh.y), dup2(bh.z), dup2(bh.w) };
            #pragma unroll
            for (int mp = 0; mp < 4; mp++)
                #pragma unroll
                for (int j = 0; j < 8; j++)
                    ffma2(acc[mp][j], ap[mp], bd[j]);
        }
    }

    float bv[8];
    #pragma unroll
    for (int j = 0; j < 8; j++) bv[j] = bias[n0 + tx * 8 + j];

    #pragma unroll
    for (int mp = 0; mp < 4; mp++) {
        int m = m0 + ty * 8 + mp * 2;
        float4 r0a = { lo2(acc[mp][0]) + bv[0], lo2(acc[mp][1]) + bv[1],
                       lo2(acc[mp][2]) + bv[2], lo2(acc[mp][3]) + bv[3] };
        float4 r0b = { lo2(acc[mp][4]) + bv[4], lo2(acc[mp][5]) + bv[5],
                       lo2(acc[mp][6]) + bv[6], lo2(acc[mp][7]) + bv[7] };
        float4 r1a = { hi2(acc[mp][0]) + bv[0], hi2(acc[mp][1]) + bv[1],
                       hi2(acc[mp][2]) + bv[2], hi2(acc[mp][3]) + bv[3] };
        float4 r1b = { hi2(acc[mp][4]) + bv[4], hi2(acc[mp][5]) + bv[5],
                       hi2(acc[mp][6]) + bv[6], hi2(acc[mp][7]) + bv[7] };
        float* c0 = C + (size_t)m * N + n0 + tx * 8;
        float* c1 = c0 + N;
        *(float4*)c0 = r0a;       *(float4*)(c0 + 4) = r0b;
        *(float4*)c1 = r1a;       *(float4*)(c1 + 4) = r1b;
    }
}

// ---------------------------------------------------------------------------
// LSTM recurrence: 16 clusters x 8 CTAs. Each CTA: 128 gate rows x 4 batches.
// W_hh slice resident in smem; h exchanged via DSMEM each step.
// ---------------------------------------------------------------------------
__global__ void __cluster_dims__(CLU, 1, 1) __launch_bounds__(NTHR, 1)
lstm_rec_kernel(const float* __restrict__ Whh, const float* __restrict__ gx,
                float* __restrict__ hs) {
    extern __shared__ float sm[];
    float* sW     = sm;                     // [ROWS][WPAD]
    float* sH0    = sm + SM_W;              // [BPC][HID]
    float* sH1    = sH0 + SM_H;
    float* sGates = sH1 + SM_H;             // [ROWS][BPC]

    const int tid  = threadIdx.x;
    const int rank = blockIdx.x % CLU;      // == cluster cta rank (cluster dim x = 8)
    const int grp  = blockIdx.x / CLU;      // batch group (4 batches)
    const int r    = tid >> 2;              // local gate row 0..127
    const int b    = tid & 3;               // batch within group
    const int gate = r >> 5;                // 0..3 (i,f,g,o)
    const int u    = r & 31;
    const int grow = gate * HID_ + rank * UPC + u;   // global gate row

    // Load W_hh slice (rows grow for all r) into smem with padded stride.
    {
        const int rr = tid >> 2, q = tid & 3;
        const int grr = (rr >> 5) * HID_ + rank * UPC + (rr & 31);
        const float4* src = (const float4*)(Whh + (size_t)grr * HID_);
        float4* dst = (float4*)(sW + rr * WPAD);
        #pragma unroll
        for (int i = 0; i < 16; i++) dst[q * 16 + i] = src[q * 16 + i];
    }
    // Zero both h buffers.
    for (int i = tid; i < 2 * SM_H; i += NTHR) sH0[i] = 0.f;
    __syncthreads();
    cluster_sync();   // buffers zeroed cluster-wide before any peer writes

    const float* gxp = gx + (size_t)((size_t)(grp * BPC + b) * S_) * G_ + grow;
    float gx_next = gxp[0];

    float c = 0.f;                          // cell state (valid for tid < 128)
    const int uu = tid >> 2, bb = tid & 3;  // update-thread unit/batch
    float* hprev = sH0;
    float* hnext = sH1;

    for (int t = 0; t < S_; t++) {
        float gcur = gx_next;
        if (t + 1 < S_) gx_next = __ldg(gxp + (size_t)(t + 1) * G_);

        // gate[r][b] = gx + dot(W[r], h_prev[b]) with packed f32x2
        const ulonglong2* Wr = (const ulonglong2*)(sW + r * WPAD);
        const ulonglong2* hb = (const ulonglong2*)(hprev + b * HID_);
        unsigned long long a0 = 0ull, a1 = 0ull;
        #pragma unroll
        for (int q = 0; q < 64; q++) {
            ulonglong2 w = Wr[q];
            ulonglong2 h = hb[q];
            ffma2(a0, w.x, h.x);
            ffma2(a1, w.y, h.y);
        }
        float acc = (lo2(a0) + hi2(a0)) + (lo2(a1) + hi2(a1));
        sGates[r * 4 + b] = gcur + acc;
        __syncthreads();

        if (tid < 128) {
            float gi = sGates[0 * 128 + tid];
            float gf = sGates[1 * 128 + tid];
            float gg = sGates[2 * 128 + tid];
            float go = sGates[3 * 128 + tid];
            gi = sigf(gi); gf = sigf(gf); gg = tanhf(gg); go = sigf(go);
            c = gf * c + gi * gg;
            float h = go * tanhf(c);

            // broadcast h to all 8 CTAs' next-buffer (incl. self)
            uint32_t loc = s2u(hnext + bb * HID_ + rank * UPC + uu);
            #pragma unroll
            for (int p = 0; p < CLU; p++) {
                uint32_t rem;
                asm volatile("mapa.shared::cluster.u32 %0, %1, %2;"
                             : "=r"(rem) : "r"(loc), "r"(p));
                asm volatile("st.shared::cluster.f32 [%0], %1;"
                             :: "r"(rem), "f"(h) : "memory");
            }
            hs[((size_t)(grp * BPC + bb) * S_ + t) * HID_ + rank * UPC + uu] = h;
        }
        cluster_sync();   // release writes / acquire peers' h
        float* tmp = hprev; hprev = hnext; hnext = tmp;
    }
}

// ---------------------------------------------------------------------------
// Output projection: out[m] = dot(hs[m], W_out) + b_out  (1 warp per row)
// ---------------------------------------------------------------------------
__global__ __launch_bounds__(256) void outproj_kernel(
    const float* __restrict__ hsbuf, const float* __restrict__ Wout,
    const float* __restrict__ bout, float* __restrict__ out) {
    const long long w = ((long long)blockIdx.x * blockDim.x + threadIdx.x) >> 5;
    const int lane = threadIdx.x & 31;
    if (w >= MS) return;
    const float4* hp = (const float4*)(hsbuf + (size_t)w * HID_);
    const float4* wp = (const float4*)Wout;
    float s = 0.f;
    #pragma unroll
    for (int q = 0; q < 2; q++) {
        float4 h = hp[lane + q * 32];
        float4 ww = wp[lane + q * 32];
        s += h.x * ww.x + h.y * ww.y + h.z * ww.z + h.w * ww.w;
    }
    #pragma unroll
    for (int off = 16; off; off >>= 1) s += __shfl_xor_sync(0xFFFFFFFFu, s, off);
    if (lane == 0) out[w] = s + bout[0];
}

// ---------------------------------------------------------------------------
// Launch
// ---------------------------------------------------------------------------
extern "C" void kernel_launch(void* const* d_in, const int* in_sizes, int n_in,
                              void* d_out, int out_size) {
    const float* in_states = (const float*)d_in[0];
    const float* W_in  = (const float*)d_in[1];
    const float* b_in  = (const float*)d_in[2];
    const float* W_ih0 = (const float*)d_in[3];
    const float* W_hh0 = (const float*)d_in[4];
    const float* b_ih0 = (const float*)d_in[5];
    const float* b_hh0 = (const float*)d_in[6];
    const float* W_ih1 = (const float*)d_in[7];
    const float* W_hh1 = (const float*)d_in[8];
    const float* b_ih1 = (const float*)d_in[9];
    const float* b_hh1 = (const float*)d_in[10];
    const float* W_out = (const float*)d_in[11];
    const float* b_out = (const float*)d_in[12];
    float* out = (float*)d_out;

    float *gx = nullptr, *hsb = nullptr, *Wc = nullptr, *b0 = nullptr, *b1 = nullptr;
    cudaGetSymbolAddress((void**)&gx,  g_gx);
    cudaGetSymbolAddress((void**)&hsb, g_hs);
    cudaGetSymbolAddress((void**)&Wc,  g_Wc);
    cudaGetSymbolAddress((void**)&b0,  g_b0);
    cudaGetSymbolAddress((void**)&b1,  g_b1);

    cudaFuncSetAttribute(lstm_rec_kernel,
                         cudaFuncAttributeMaxDynamicSharedMemorySize, (int)REC_SMEM);

    // 1) fused weights/biases
    prep_kernel<<<(G_ * F_ + 255) / 256, 256>>>(W_ih0, W_in, b_in, b_ih0, b_hh0, b_ih1, b_hh1);

    dim3 ggrid(G_ / 128, (unsigned)(MS / 128));   // (8, 1024)

    // 2) gx0 = in_states @ Wc^T + b0     (K = 40)
    gemm_bias_f32<<<ggrid, 256>>>(in_states, Wc, b0, gx, F_, G_);

    // 3) layer-0 recurrence -> hs
    lstm_rec_kernel<<<(B_ / BPC) * CLU, NTHR, REC_SMEM>>>(W_hh0, gx, hsb);

    // 4) gx1 = hs @ W_ih1^T + b1        (K = 256)
    gemm_bias_f32<<<ggrid, 256>>>(hsb, W_ih1, b1, gx, HID_, G_);

    // 5) layer-1 recurrence -> hs (overwrites hs0, already consumed)
    lstm_rec_kernel<<<(B_ / BPC) * CLU, NTHR, REC_SMEM>>>(W_hh1, gx, hsb);

    // 6) output projection
    outproj_kernel<<<(unsigned)(MS / 8), 256>>>(hsb, W_out, b_out, out);
}

// round 5
// speedup vs baseline: 4.0889x; 4.0889x over previous
#include <cuda_runtime.h>
#include <cstdint>
#include <cstddef>

#define DI __device__ __forceinline__

// ---------------------------------------------------------------------------
// Problem constants
// ---------------------------------------------------------------------------
namespace {
constexpr int B_   = 64;
constexpr int S_   = 2048;
constexpr int F_   = 40;
constexpr int EMB_ = 128;
constexpr int HID_ = 256;
constexpr int G_   = 4 * HID_;             // 1024 gate rows
constexpr long long MS = (long long)B_ * S_;   // 131072 flattened rows

// Recurrence kernel geometry
constexpr int CLU  = 8;                    // CTAs per cluster
constexpr int UPC  = HID_ / CLU;           // 32 hidden units per CTA
constexpr int ROWS = 4 * UPC;              // 128 gate rows per CTA
constexpr int BPC  = 4;                    // batch rows per cluster
constexpr int NTHR = 512;                  // 128 rows x 4 k-chunks
}

// ---------------------------------------------------------------------------
// Scratch (device globals: no runtime allocation allowed)
// ---------------------------------------------------------------------------
__device__ float g_gx[(size_t)MS * G_];     // 536 MB: gate preactivations (reused L0/L1)
__device__ float g_hs[(size_t)MS * HID_];   // 134 MB: hidden states (reused L0/L1)
__device__ float g_Wc[G_ * F_];             // fused W_ih0 @ W_in
__device__ float g_b0[G_];                  // fused layer-0 bias
__device__ float g_b1[G_];                  // layer-1 bias

// ---------------------------------------------------------------------------
// f32x2 helpers (packed dual-FMA; ptxas won't emit from C++)
// ---------------------------------------------------------------------------
DI void ffma2(unsigned long long& acc, unsigned long long a, unsigned long long b) {
    asm("fma.rn.f32x2 %0, %1, %2, %0;" : "+l"(acc) : "l"(a), "l"(b));
}
DI unsigned long long dup2(float x) {
    unsigned long long d;
    unsigned u = __float_as_uint(x);
    asm("mov.b64 %0, {%1, %1};" : "=l"(d) : "r"(u));
    return d;
}
DI float lo2(unsigned long long v) { return __uint_as_float((unsigned)v); }
DI float hi2(unsigned long long v) { return __uint_as_float((unsigned)(v >> 32)); }

DI uint32_t s2u(const void* p) {
    uint32_t a;
    asm("{ .reg .u64 t; cvta.to.shared.u64 t, %1; cvt.u32.u64 %0, t; }"
        : "=r"(a) : "l"(p));
    return a;
}
DI void cluster_sync() {
    asm volatile("barrier.cluster.arrive.aligned;" ::: "memory");
    asm volatile("barrier.cluster.wait.aligned;" ::: "memory");
}
DI float sigf(float x) { return 1.f / (1.f + __expf(-x)); }

// ---------------------------------------------------------------------------
// Prep: Wc = W_ih0 @ W_in  (1024 x 40), fused biases
// ---------------------------------------------------------------------------
__global__ void prep_kernel(const float* __restrict__ Wih0, const float* __restrict__ Win,
                            const float* __restrict__ bin,
                            const float* __restrict__ bih0, const float* __restrict__ bhh0,
                            const float* __restrict__ bih1, const float* __restrict__ bhh1) {
    int idx = blockIdx.x * blockDim.x + threadIdx.x;
    if (idx < G_ * F_) {
        int g = idx / F_, f = idx % F_;
        float s = 0.f;
        #pragma unroll 8
        for (int e = 0; e < EMB_; e++) s += Wih0[g * EMB_ + e] * Win[e * F_ + f];
        g_Wc[idx] = s;
    }
    if (idx < G_) {
        float s = bih0[idx] + bhh0[idx];
        #pragma unroll 8
        for (int e = 0; e < EMB_; e++) s += Wih0[idx * EMB_ + e] * bin[e];
        g_b0[idx] = s;
        g_b1[idx] = bih1[idx] + bhh1[idx];
    }
}

// ---------------------------------------------------------------------------
// GEMM: C[M][N] = A[M][K] @ Bt[N][K] + bias[N]
// 128x128 tile, 256 threads, 8x8 per thread (f32x2 on M-pairs). K % 8 == 0.
// ---------------------------------------------------------------------------
__global__ __launch_bounds__(256) void gemm_bias_f32(
    const float* __restrict__ A, const float* __restrict__ Bt,
    const float* __restrict__ bias, float* __restrict__ C, int K, int N) {
    __shared__ float As[8][128];   // [k][m]
    __shared__ float Bs[8][128];   // [k][n]

    const int tid = threadIdx.x;
    const int m0 = blockIdx.y * 128, n0 = blockIdx.x * 128;
    const int lr = tid >> 1, lq = tid & 1;     // load: row, half (2 float4/row/chunk)
    const int ty = tid >> 4, tx = tid & 15;    // compute: 16x16

    unsigned long long acc[4][8];
    #pragma unroll
    for (int i = 0; i < 4; i++)
        #pragma unroll
        for (int j = 0; j < 8; j++) acc[i][j] = 0ull;

    for (int kc = 0; kc < K; kc += 8) {
        float4 av = *(const float4*)(A + (size_t)(m0 + lr) * K + kc + lq * 4);
        float4 bv = *(const float4*)(Bt + (size_t)(n0 + lr) * K + kc + lq * 4);
        __syncthreads();   // previous chunk's compute done before overwrite
        As[lq * 4 + 0][lr] = av.x; As[lq * 4 + 1][lr] = av.y;
        As[lq * 4 + 2][lr] = av.z; As[lq * 4 + 3][lr] = av.w;
        Bs[lq * 4 + 0][lr] = bv.x; Bs[lq * 4 + 1][lr] = bv.y;
        Bs[lq * 4 + 2][lr] = bv.z; Bs[lq * 4 + 3][lr] = bv.w;
        __syncthreads();
        #pragma unroll
        for (int k = 0; k < 8; k++) {
            ulonglong2 a01 = *(const ulonglong2*)&As[k][ty * 8];
            ulonglong2 a23 = *(const ulonglong2*)&As[k][ty * 8 + 4];
            float4 bl = *(const float4*)&Bs[k][tx * 8];
            float4 bh = *(const float4*)&Bs[k][tx * 8 + 4];
            unsigned long long ap[4] = { a01.x, a01.y, a23.x, a23.y };
            unsigned long long bd[8] = { dup2(bl.x), dup2(bl.y), dup2(bl.z), dup2(bl.w),
                                         dup2(bh.x), dup2(bh.y), dup2(bh.z), dup2(bh.w) };
            #pragma unroll
            for (int mp = 0; mp < 4; mp++)
                #pragma unroll
                for (int j = 0; j < 8; j++)
                    ffma2(acc[mp][j], ap[mp], bd[j]);
        }
    }

    float bv[8];
    #pragma unroll
    for (int j = 0; j < 8; j++) bv[j] = bias[n0 + tx * 8 + j];

    #pragma unroll
    for (int mp = 0; mp < 4; mp++) {
        int m = m0 + ty * 8 + mp * 2;
        float4 r0a = { lo2(acc[mp][0]) + bv[0], lo2(acc[mp][1]) + bv[1],
                       lo2(acc[mp][2]) + bv[2], lo2(acc[mp][3]) + bv[3] };
        float4 r0b = { lo2(acc[mp][4]) + bv[4], lo2(acc[mp][5]) + bv[5],
                       lo2(acc[mp][6]) + bv[6], lo2(acc[mp][7]) + bv[7] };
        float4 r1a = { hi2(acc[mp][0]) + bv[0], hi2(acc[mp][1]) + bv[1],
                       hi2(acc[mp][2]) + bv[2], hi2(acc[mp][3]) + bv[3] };
        float4 r1b = { hi2(acc[mp][4]) + bv[4], hi2(acc[mp][5]) + bv[5],
                       hi2(acc[mp][6]) + bv[6], hi2(acc[mp][7]) + bv[7] };
        float* c0 = C + (size_t)m * N + n0 + tx * 8;
        float* c1 = c0 + N;
        *(float4*)c0 = r0a;       *(float4*)(c0 + 4) = r0b;
        *(float4*)c1 = r1a;       *(float4*)(c1 + 4) = r1b;
    }
}

// ---------------------------------------------------------------------------
// LSTM recurrence v2: W_hh slice in REGISTERS.
// 16 clusters x 8 CTAs. Thread (r = tid&127, ks = tid>>7) holds
// W[grow][ks*64 .. ks*64+63] in 64 regs; computes 4 batch partials per step.
// h lives in smem as [b][256], broadcast-read (all lanes same address).
// Cross-ks reduction via smem; 128 update threads run the cell + DSMEM bcast.
// ---------------------------------------------------------------------------
__global__ void __cluster_dims__(CLU, 1, 1) __launch_bounds__(NTHR, 1)
lstm_rec_kernel(const float* __restrict__ Whh, const float* __restrict__ gx,
                float* __restrict__ hs) {
    __shared__ float sH[2][BPC][HID_];       // double-buffered hidden state
    __shared__ float sRed[4][ROWS][4];       // [ks][r][b] partial sums

    const int tid  = threadIdx.x;
    const int rank = blockIdx.x % CLU;       // cluster cta rank
    const int grp  = blockIdx.x / CLU;       // batch group (4 batches)
    const int r    = tid & 127;              // local gate row
    const int ks   = tid >> 7;               // k-chunk 0..3
    const int gate = r >> 5;
    const int u    = r & 31;
    const int grow = gate * HID_ + rank * UPC + u;   // global gate row

    // --- W slice into registers: 64 floats = 32 packed f32x2 pairs ---
    unsigned long long w[32];
    {
        const float4* src = (const float4*)(Whh + (size_t)grow * HID_ + ks * 64);
        #pragma unroll
        for (int i = 0; i < 16; i++) {
            float4 v = src[i];
            ulonglong2 p = *(const ulonglong2*)&v;
            w[2 * i]     = p.x;
            w[2 * i + 1] = p.y;
        }
    }

    // Zero both h buffers.
    for (int i = tid; i < 2 * BPC * HID_; i += NTHR) (&sH[0][0][0])[i] = 0.f;
    __syncthreads();
    cluster_sync();     // zeroed cluster-wide before any peer writes

    // Update-thread state (tid < 128): unit uu, batch bb.
    const int uu = tid >> 2, bb = tid & 3;
    float c = 0.f;
    float gxn[4];
    const float* gxbase = gx + (size_t)(grp * BPC + bb) * S_ * G_ + rank * UPC + uu;
    if (tid < 128) {
        #pragma unroll
        for (int g = 0; g < 4; g++) gxn[g] = __ldg(gxbase + g * HID_);
    }

    int cur = 0;
    for (int t = 0; t < S_; t++) {
        // ---- partial dot products: 4 batches x 64-K chunk, W in regs ----
        const float* hp = &sH[cur][0][0];
        const ulonglong2* h0 = (const ulonglong2*)(hp + 0 * HID_ + ks * 64);
        const ulonglong2* h1 = (const ulonglong2*)(hp + 1 * HID_ + ks * 64);
        const ulonglong2* h2 = (const ulonglong2*)(hp + 2 * HID_ + ks * 64);
        const ulonglong2* h3 = (const ulonglong2*)(hp + 3 * HID_ + ks * 64);
        unsigned long long a0 = 0ull, a1 = 0ull, a2 = 0ull, a3 = 0ull;
        #pragma unroll
        for (int q = 0; q < 16; q++) {
            ulonglong2 x0 = h0[q], x1 = h1[q], x2 = h2[q], x3 = h3[q];
            ffma2(a0, w[2 * q], x0.x); ffma2(a0, w[2 * q + 1], x0.y);
            ffma2(a1, w[2 * q], x1.x); ffma2(a1, w[2 * q + 1], x1.y);
            ffma2(a2, w[2 * q], x2.x); ffma2(a2, w[2 * q + 1], x2.y);
            ffma2(a3, w[2 * q], x3.x); ffma2(a3, w[2 * q + 1], x3.y);
        }
        float4 pv = { lo2(a0) + hi2(a0), lo2(a1) + hi2(a1),
                      lo2(a2) + hi2(a2), lo2(a3) + hi2(a3) };
        *(float4*)&sRed[ks][r][0] = pv;
        __syncthreads();

        // ---- cell update on 128 threads ----
        if (tid < 128) {
            float gates[4];
            #pragma unroll
            for (int g = 0; g < 4; g++) {
                int rr = g * 32 + uu;
                gates[g] = gxn[g] + sRed[0][rr][bb] + sRed[1][rr][bb]
                                  + sRed[2][rr][bb] + sRed[3][rr][bb];
            }
            if (t + 1 < S_) {
                const float* gp = gxbase + (size_t)(t + 1) * G_;
                #pragma unroll
                for (int g = 0; g < 4; g++) gxn[g] = __ldg(gp + g * HID_);
            }
            float gi = sigf(gates[0]);
            float gf = sigf(gates[1]);
            float gg = tanhf(gates[2]);
            float go = sigf(gates[3]);
            c = gf * c + gi * gg;
            float h = go * tanhf(c);

            // broadcast h to all 8 CTAs' next buffer (incl. self)
            uint32_t loc = s2u(&sH[cur ^ 1][bb][rank * UPC + uu]);
            #pragma unroll
            for (int p = 0; p < CLU; p++) {
                uint32_t rem;
                asm volatile("mapa.shared::cluster.u32 %0, %1, %2;"
                             : "=r"(rem) : "r"(loc), "r"(p));
                asm volatile("st.shared::cluster.f32 [%0], %1;"
                             :: "r"(rem), "f"(h) : "memory");
            }
            hs[((size_t)(grp * BPC + bb) * S_ + t) * HID_ + rank * UPC + uu] = h;
        }
        cluster_sync();    // release h writes cluster-wide
        cur ^= 1;
    }
}

// ---------------------------------------------------------------------------
// Output projection: out[m] = dot(hs[m], W_out) + b_out  (1 warp per row)
// ---------------------------------------------------------------------------
__global__ __launch_bounds__(256) void outproj_kernel(
    const float* __restrict__ hsbuf, const float* __restrict__ Wout,
    const float* __restrict__ bout, float* __restrict__ out) {
    const long long w = ((long long)blockIdx.x * blockDim.x + threadIdx.x) >> 5;
    const int lane = threadIdx.x & 31;
    if (w >= MS) return;
    const float4* hp = (const float4*)(hsbuf + (size_t)w * HID_);
    const float4* wp = (const float4*)Wout;
    float s = 0.f;
    #pragma unroll
    for (int q = 0; q < 2; q++) {
        float4 h = hp[lane + q * 32];
        float4 ww = wp[lane + q * 32];
        s += h.x * ww.x + h.y * ww.y + h.z * ww.z + h.w * ww.w;
    }
    #pragma unroll
    for (int off = 16; off; off >>= 1) s += __shfl_xor_sync(0xFFFFFFFFu, s, off);
    if (lane == 0) out[w] = s + bout[0];
}

// ---------------------------------------------------------------------------
// Launch
// ---------------------------------------------------------------------------
extern "C" void kernel_launch(void* const* d_in, const int* in_sizes, int n_in,
                              void* d_out, int out_size) {
    const float* in_states = (const float*)d_in[0];
    const float* W_in  = (const float*)d_in[1];
    const float* b_in  = (const float*)d_in[2];
    const float* W_ih0 = (const float*)d_in[3];
    const float* W_hh0 = (const float*)d_in[4];
    const float* b_ih0 = (const float*)d_in[5];
    const float* b_hh0 = (const float*)d_in[6];
    const float* W_ih1 = (const float*)d_in[7];
    const float* W_hh1 = (const float*)d_in[8];
    const float* b_ih1 = (const float*)d_in[9];
    const float* b_hh1 = (const float*)d_in[10];
    const float* W_out = (const float*)d_in[11];
    const float* b_out = (const float*)d_in[12];
    float* out = (float*)d_out;

    float *gx = nullptr, *hsb = nullptr, *Wc = nullptr, *b0 = nullptr, *b1 = nullptr;
    cudaGetSymbolAddress((void**)&gx,  g_gx);
    cudaGetSymbolAddress((void**)&hsb, g_hs);
    cudaGetSymbolAddress((void**)&Wc,  g_Wc);
    cudaGetSymbolAddress((void**)&b0,  g_b0);
    cudaGetSymbolAddress((void**)&b1,  g_b1);

    // 1) fused weights/biases
    prep_kernel<<<(G_ * F_ + 255) / 256, 256>>>(W_ih0, W_in, b_in, b_ih0, b_hh0, b_ih1, b_hh1);

    dim3 ggrid(G_ / 128, (unsigned)(MS / 128));   // (8, 1024)

    // 2) gx0 = in_states @ Wc^T + b0     (K = 40)
    gemm_bias_f32<<<ggrid, 256>>>(in_states, Wc, b0, gx, F_, G_);

    // 3) layer-0 recurrence -> hs
    lstm_rec_kernel<<<(B_ / BPC) * CLU, NTHR>>>(W_hh0, gx, hsb);

    // 4) gx1 = hs @ W_ih1^T + b1        (K = 256)
    gemm_bias_f32<<<ggrid, 256>>>(hsb, W_ih1, b1, gx, HID_, G_);

    // 5) layer-1 recurrence -> hs (overwrites hs0, already consumed)
    lstm_rec_kernel<<<(B_ / BPC) * CLU, NTHR>>>(W_hh1, gx, hsb);

    // 6) output projection
    outproj_kernel<<<(unsigned)(MS / 8), 256>>>(hsb, W_out, b_out, out);
}

// round 6
// speedup vs baseline: 4.6758x; 1.1435x over previous
#include <cuda_runtime.h>
#include <cstdint>
#include <cstddef>

#define DI __device__ __forceinline__

// ---------------------------------------------------------------------------
// Problem constants
// ---------------------------------------------------------------------------
namespace {
constexpr int B_   = 64;
constexpr int S_   = 2048;
constexpr int F_   = 40;
constexpr int EMB_ = 128;
constexpr int HID_ = 256;
constexpr int G_   = 4 * HID_;             // 1024 gate rows
constexpr long long MS = (long long)B_ * S_;   // 131072 flattened rows

// Recurrence kernel geometry
constexpr int CLU  = 8;                    // CTAs per cluster
constexpr int UPC  = HID_ / CLU;           // 32 hidden units per CTA
constexpr int ROWS = 4 * UPC;              // 128 gate rows per CTA
constexpr int BPC  = 4;                    // batch rows per cluster
constexpr int NTHR = 512;                  // 128 rows x 4 k-chunks
}

// ---------------------------------------------------------------------------
// Scratch (device globals: no runtime allocation allowed)
// ---------------------------------------------------------------------------
__device__ float g_gx[(size_t)MS * G_];     // 536 MB: gate preactivations (reused L0/L1)
__device__ float g_hs[(size_t)MS * HID_];   // 134 MB: hidden states (reused L0/L1)
__device__ float g_Wc[G_ * F_];             // fused W_ih0 @ W_in
__device__ float g_b0[G_];                  // fused layer-0 bias
__device__ float g_b1[G_];                  // layer-1 bias

// ---------------------------------------------------------------------------
// f32x2 helpers (packed dual-FMA; ptxas won't emit from C++)
// ---------------------------------------------------------------------------
DI void ffma2(unsigned long long& acc, unsigned long long a, unsigned long long b) {
    asm("fma.rn.f32x2 %0, %1, %2, %0;" : "+l"(acc) : "l"(a), "l"(b));
}
DI unsigned long long dup2(float x) {
    unsigned long long d;
    unsigned u = __float_as_uint(x);
    asm("mov.b64 %0, {%1, %1};" : "=l"(d) : "r"(u));
    return d;
}
DI float lo2(unsigned long long v) { return __uint_as_float((unsigned)v); }
DI float hi2(unsigned long long v) { return __uint_as_float((unsigned)(v >> 32)); }

DI uint32_t s2u(const void* p) {
    uint32_t a;
    asm("{ .reg .u64 t; cvta.to.shared.u64 t, %1; cvt.u32.u64 %0, t; }"
        : "=r"(a) : "l"(p));
    return a;
}
DI void cluster_sync() {
    asm volatile("barrier.cluster.arrive.aligned;" ::: "memory");
    asm volatile("barrier.cluster.wait.aligned;" ::: "memory");
}

// Fast activations: EX2/RCP approx (1-2 ulp), saturation-safe at +/-inf.
DI float fex2(float x) { float y; asm("ex2.approx.f32 %0, %1;" : "=f"(y) : "f"(x)); return y; }
DI float frcp(float x) { float y; asm("rcp.approx.f32 %0, %1;" : "=f"(y) : "f"(x)); return y; }
constexpr float LOG2E_ = 1.4426950408889634f;
DI float sigf(float x)  { return frcp(1.f + fex2(-x * LOG2E_)); }          // x->-inf: rcp(inf)=0; x->inf: 1
DI float tanhfast(float x) { return 1.f - 2.f * frcp(1.f + fex2(x * (2.f * LOG2E_))); }  // inf-safe

// ---------------------------------------------------------------------------
// Prep: Wc = W_ih0 @ W_in  (1024 x 40), fused biases
// ---------------------------------------------------------------------------
__global__ void prep_kernel(const float* __restrict__ Wih0, const float* __restrict__ Win,
                            const float* __restrict__ bin,
                            const float* __restrict__ bih0, const float* __restrict__ bhh0,
                            const float* __restrict__ bih1, const float* __restrict__ bhh1) {
    int idx = blockIdx.x * blockDim.x + threadIdx.x;
    if (idx < G_ * F_) {
        int g = idx / F_, f = idx % F_;
        float s = 0.f;
        #pragma unroll 8
        for (int e = 0; e < EMB_; e++) s += Wih0[g * EMB_ + e] * Win[e * F_ + f];
        g_Wc[idx] = s;
    }
    if (idx < G_) {
        float s = bih0[idx] + bhh0[idx];
        #pragma unroll 8
        for (int e = 0; e < EMB_; e++) s += Wih0[idx * EMB_ + e] * bin[e];
        g_b0[idx] = s;
        g_b1[idx] = bih1[idx] + bhh1[idx];
    }
}

// No-op kernel: shifts launch indices so ncu's capture slot lands on lstm_rec.
__global__ void noop_kernel() {}

// ---------------------------------------------------------------------------
// GEMM: C[M][N] = A[M][K] @ Bt[N][K] + bias[N]
// 128x128 tile, 256 threads, 8x8 per thread (f32x2 on M-pairs). K % 8 == 0.
// ---------------------------------------------------------------------------
__global__ __launch_bounds__(256) void gemm_bias_f32(
    const float* __restrict__ A, const float* __restrict__ Bt,
    const float* __restrict__ bias, float* __restrict__ C, int K, int N) {
    __shared__ float As[8][128];   // [k][m]
    __shared__ float Bs[8][128];   // [k][n]

    const int tid = threadIdx.x;
    const int m0 = blockIdx.y * 128, n0 = blockIdx.x * 128;
    const int lr = tid >> 1, lq = tid & 1;     // load: row, half (2 float4/row/chunk)
    const int ty = tid >> 4, tx = tid & 15;    // compute: 16x16

    unsigned long long acc[4][8];
    #pragma unroll
    for (int i = 0; i < 4; i++)
        #pragma unroll
        for (int j = 0; j < 8; j++) acc[i][j] = 0ull;

    for (int kc = 0; kc < K; kc += 8) {
        float4 av = *(const float4*)(A + (size_t)(m0 + lr) * K + kc + lq * 4);
        float4 bv = *(const float4*)(Bt + (size_t)(n0 + lr) * K + kc + lq * 4);
        __syncthreads();   // previous chunk's compute done before overwrite
        As[lq * 4 + 0][lr] = av.x; As[lq * 4 + 1][lr] = av.y;
        As[lq * 4 + 2][lr] = av.z; As[lq * 4 + 3][lr] = av.w;
        Bs[lq * 4 + 0][lr] = bv.x; Bs[lq * 4 + 1][lr] = bv.y;
        Bs[lq * 4 + 2][lr] = bv.z; Bs[lq * 4 + 3][lr] = bv.w;
        __syncthreads();
        #pragma unroll
        for (int k = 0; k < 8; k++) {
            ulonglong2 a01 = *(const ulonglong2*)&As[k][ty * 8];
            ulonglong2 a23 = *(const ulonglong2*)&As[k][ty * 8 + 4];
            float4 bl = *(const float4*)&Bs[k][tx * 8];
            float4 bh = *(const float4*)&Bs[k][tx * 8 + 4];
            unsigned long long ap[4] = { a01.x, a01.y, a23.x, a23.y };
            unsigned long long bd[8] = { dup2(bl.x), dup2(bl.y), dup2(bl.z), dup2(bl.w),
                                         dup2(bh.x), dup2(bh.y), dup2(bh.z), dup2(bh.w) };
            #pragma unroll
            for (int mp = 0; mp < 4; mp++)
                #pragma unroll
                for (int j = 0; j < 8; j++)
                    ffma2(acc[mp][j], ap[mp], bd[j]);
        }
    }

    float bv[8];
    #pragma unroll
    for (int j = 0; j < 8; j++) bv[j] = bias[n0 + tx * 8 + j];

    #pragma unroll
    for (int mp = 0; mp < 4; mp++) {
        int m = m0 + ty * 8 + mp * 2;
        float4 r0a = { lo2(acc[mp][0]) + bv[0], lo2(acc[mp][1]) + bv[1],
                       lo2(acc[mp][2]) + bv[2], lo2(acc[mp][3]) + bv[3] };
        float4 r0b = { lo2(acc[mp][4]) + bv[4], lo2(acc[mp][5]) + bv[5],
                       lo2(acc[mp][6]) + bv[6], lo2(acc[mp][7]) + bv[7] };
        float4 r1a = { hi2(acc[mp][0]) + bv[0], hi2(acc[mp][1]) + bv[1],
                       hi2(acc[mp][2]) + bv[2], hi2(acc[mp][3]) + bv[3] };
        float4 r1b = { hi2(acc[mp][4]) + bv[4], hi2(acc[mp][5]) + bv[5],
                       hi2(acc[mp][6]) + bv[6], hi2(acc[mp][7]) + bv[7] };
        float* c0 = C + (size_t)m * N + n0 + tx * 8;
        float* c1 = c0 + N;
        *(float4*)c0 = r0a;       *(float4*)(c0 + 4) = r0b;
        *(float4*)c1 = r1a;       *(float4*)(c1 + 4) = r1b;
    }
}

// ---------------------------------------------------------------------------
// LSTM recurrence v3: W_hh slice in registers, 2-batch dot passes (lower reg
// pressure), fast activations. 16 clusters x 8 CTAs, h exchange via DSMEM.
// ---------------------------------------------------------------------------
__global__ void __cluster_dims__(CLU, 1, 1) __launch_bounds__(NTHR, 1)
lstm_rec_kernel(const float* __restrict__ Whh, const float* __restrict__ gx,
                float* __restrict__ hs) {
    __shared__ float sH[2][BPC][HID_];       // double-buffered hidden state
    __shared__ float sRed[4][ROWS][4];       // [ks][r][b] partial sums

    const int tid  = threadIdx.x;
    const int rank = blockIdx.x % CLU;       // cluster cta rank
    const int grp  = blockIdx.x / CLU;       // batch group (4 batches)
    const int r    = tid & 127;              // local gate row
    const int ks   = tid >> 7;               // k-chunk 0..3
    const int gate = r >> 5;
    const int u    = r & 31;
    const int grow = gate * HID_ + rank * UPC + u;   // global gate row

    // --- W slice into registers: 64 floats = 32 packed f32x2 pairs ---
    unsigned long long w[32];
    {
        const float4* src = (const float4*)(Whh + (size_t)grow * HID_ + ks * 64);
        #pragma unroll
        for (int i = 0; i < 16; i++) {
            float4 v = src[i];
            ulonglong2 p = *(const ulonglong2*)&v;
            w[2 * i]     = p.x;
            w[2 * i + 1] = p.y;
        }
    }

    // Zero both h buffers.
    for (int i = tid; i < 2 * BPC * HID_; i += NTHR) (&sH[0][0][0])[i] = 0.f;
    __syncthreads();
    cluster_sync();     // zeroed cluster-wide before any peer writes

    // Update-thread state (tid < 128): unit uu, batch bb.
    const int uu = tid >> 2, bb = tid & 3;
    float c = 0.f;
    float gxn[4];
    const float* gxbase = gx + (size_t)(grp * BPC + bb) * S_ * G_ + rank * UPC + uu;
    if (tid < 128) {
        #pragma unroll
        for (int g = 0; g < 4; g++) gxn[g] = __ldg(gxbase + g * HID_);
    }

    int cur = 0;
    for (int t = 0; t < S_; t++) {
        // ---- partial dots: two passes of 2 batches (bounded reg pressure) ----
        const float* hp = &sH[cur][0][0];
        float red[4];
        #pragma unroll
        for (int bp = 0; bp < 2; bp++) {
            const ulonglong2* hA = (const ulonglong2*)(hp + (2 * bp + 0) * HID_ + ks * 64);
            const ulonglong2* hB = (const ulonglong2*)(hp + (2 * bp + 1) * HID_ + ks * 64);
            unsigned long long s0 = 0ull, s1 = 0ull, s2 = 0ull, s3 = 0ull;
            #pragma unroll
            for (int q = 0; q < 16; q++) {
                ulonglong2 xA = hA[q];
                ulonglong2 xB = hB[q];
                ffma2(s0, w[2 * q],     xA.x);
                ffma2(s1, w[2 * q + 1], xA.y);
                ffma2(s2, w[2 * q],     xB.x);
                ffma2(s3, w[2 * q + 1], xB.y);
            }
            red[2 * bp + 0] = (lo2(s0) + hi2(s0)) + (lo2(s1) + hi2(s1));
            red[2 * bp + 1] = (lo2(s2) + hi2(s2)) + (lo2(s3) + hi2(s3));
        }
        float4 pv = { red[0], red[1], red[2], red[3] };
        *(float4*)&sRed[ks][r][0] = pv;
        __syncthreads();

        // ---- cell update on 128 threads ----
        if (tid < 128) {
            float gates[4];
            #pragma unroll
            for (int g = 0; g < 4; g++) {
                int rr = g * 32 + uu;
                gates[g] = gxn[g] + sRed[0][rr][bb] + sRed[1][rr][bb]
                                  + sRed[2][rr][bb] + sRed[3][rr][bb];
            }
            if (t + 1 < S_) {
                const float* gp = gxbase + (size_t)(t + 1) * G_;
                #pragma unroll
                for (int g = 0; g < 4; g++) gxn[g] = __ldg(gp + g * HID_);
            }
            float gi = sigf(gates[0]);
            float gf = sigf(gates[1]);
            float gg = tanhfast(gates[2]);
            float go = sigf(gates[3]);
            c = gf * c + gi * gg;
            float h = go * tanhfast(c);

            // broadcast h to all 8 CTAs' next buffer (incl. self)
            uint32_t loc = s2u(&sH[cur ^ 1][bb][rank * UPC + uu]);
            #pragma unroll
            for (int p = 0; p < CLU; p++) {
                uint32_t rem;
                asm volatile("mapa.shared::cluster.u32 %0, %1, %2;"
                             : "=r"(rem) : "r"(loc), "r"(p));
                asm volatile("st.shared::cluster.f32 [%0], %1;"
                             :: "r"(rem), "f"(h) : "memory");
            }
            hs[((size_t)(grp * BPC + bb) * S_ + t) * HID_ + rank * UPC + uu] = h;
        }
        cluster_sync();    // release h writes cluster-wide
        cur ^= 1;
    }
}

// ---------------------------------------------------------------------------
// Output projection: out[m] = dot(hs[m], W_out) + b_out  (1 warp per row)
// ---------------------------------------------------------------------------
__global__ __launch_bounds__(256) void outproj_kernel(
    const float* __restrict__ hsbuf, const float* __restrict__ Wout,
    const float* __restrict__ bout, float* __restrict__ out) {
    const long long w = ((long long)blockIdx.x * blockDim.x + threadIdx.x) >> 5;
    const int lane = threadIdx.x & 31;
    if (w >= MS) return;
    const float4* hp = (const float4*)(hsbuf + (size_t)w * HID_);
    const float4* wp = (const float4*)Wout;
    float s = 0.f;
    #pragma unroll
    for (int q = 0; q < 2; q++) {
        float4 h = hp[lane + q * 32];
        float4 ww = wp[lane + q * 32];
        s += h.x * ww.x + h.y * ww.y + h.z * ww.z + h.w * ww.w;
    }
    #pragma unroll
    for (int off = 16; off; off >>= 1) s += __shfl_xor_sync(0xFFFFFFFFu, s, off);
    if (lane == 0) out[w] = s + bout[0];
}

// ---------------------------------------------------------------------------
// Launch
// ---------------------------------------------------------------------------
extern "C" void kernel_launch(void* const* d_in, const int* in_sizes, int n_in,
                              void* d_out, int out_size) {
    const float* in_states = (const float*)d_in[0];
    const float* W_in  = (const float*)d_in[1];
    const float* b_in  = (const float*)d_in[2];
    const float* W_ih0 = (const float*)d_in[3];
    const float* W_hh0 = (const float*)d_in[4];
    const float* b_ih0 = (const float*)d_in[5];
    const float* b_hh0 = (const float*)d_in[6];
    const float* W_ih1 = (const float*)d_in[7];
    const float* W_hh1 = (const float*)d_in[8];
    const float* b_ih1 = (const float*)d_in[9];
    const float* b_hh1 = (const float*)d_in[10];
    const float* W_out = (const float*)d_in[11];
    const float* b_out = (const float*)d_in[12];
    float* out = (float*)d_out;

    float *gx = nullptr, *hsb = nullptr, *Wc = nullptr, *b0 = nullptr, *b1 = nullptr;
    cudaGetSymbolAddress((void**)&gx,  g_gx);
    cudaGetSymbolAddress((void**)&hsb, g_hs);
    cudaGetSymbolAddress((void**)&Wc,  g_Wc);
    cudaGetSymbolAddress((void**)&b0,  g_b0);
    cudaGetSymbolAddress((void**)&b1,  g_b1);

    // 1) fused weights/biases
    prep_kernel<<<(G_ * F_ + 255) / 256, 256>>>(W_ih0, W_in, b_in, b_ih0, b_hh0, b_ih1, b_hh1);

    dim3 ggrid(G_ / 128, (unsigned)(MS / 128));   // (8, 1024)

    // 2) gx0 = in_states @ Wc^T + b0     (K = 40)
    gemm_bias_f32<<<ggrid, 256>>>(in_states, Wc, b0, gx, F_, G_);

    // dummy launch: shifts the ncu capture slot onto lstm_rec (index alignment)
    noop_kernel<<<1, 32>>>();

    // 3) layer-0 recurrence -> hs
    lstm_rec_kernel<<<(B_ / BPC) * CLU, NTHR>>>(W_hh0, gx, hsb);

    // 4) gx1 = hs @ W_ih1^T + b1        (K = 256)
    gemm_bias_f32<<<ggrid, 256>>>(hsb, W_ih1, b1, gx, HID_, G_);

    // 5) layer-1 recurrence -> hs (overwrites hs0, already consumed)
    lstm_rec_kernel<<<(B_ / BPC) * CLU, NTHR>>>(W_hh1, gx, hsb);

    // 6) output projection
    outproj_kernel<<<(unsigned)(MS / 8), 256>>>(hsb, W_out, b_out, out);
}